// round 14
// baseline (speedup 1.0000x reference)
#include <cuda_runtime.h>
#include <math.h>

#define NTH 640
#define NWARP 20
#define TW  248           // outputs per block; row width 256 = 2 warp-spans

constexpr int NTOT = 2097152;
constexpr int NOUT = NTOT - 6;
constexpr int ST2  = 256;  // activation row stride (floats)

// ---- weight scratch layout (floats); transposed oc-contiguous ----
constexpr int O_W1  = 0;                 // 100   w1[oc][k]
constexpr int O_B1  = 100;               // 20
constexpr int O_W2T = 120;               // 4000  T2[(ic*5+k)*40 + oc]
constexpr int O_B2  = 4120;              // 40
constexpr int O_W3T = 4160;              // 3200  T3[ic*80 + oc]
constexpr int O_B3  = 7360;              // 80
constexpr int O_W4T = 7440;              // 3200  T4[ic*40 + oc]
constexpr int O_B4  = 10640;             // 40
constexpr int O_W5T = 10680;             // 2400  T5[(ic*3+k)*20 + oc]
constexpr int O_B5  = 13080;             // 20
constexpr int O_W6  = 13100;             // 20
constexpr int O_B6  = 13120;             // 1 (+3 pad)
constexpr int NWT   = 13124;             // total weight floats (divisible by 4)
// ---- activation area (shared memory) ----
constexpr int O_UU  = 13124;             // alloc 264 (need TW+14=262)
constexpr int O_DIF = O_UU + 264;        // alloc 264 (need TW+12=260)
constexpr int O_BM  = O_DIF + 264;       // alloc 256 (need TW+2=250)
constexpr int O_Y   = O_BM + 256;        // 40*ST2  (A2, A4)
constexpr int O_X   = O_Y + 40 * ST2;    // 80*ST2  (A1 rows 0-19, A3 all, A5 rows 0-19)
constexpr int SMEM_FLOATS = O_X + 80 * ST2;
constexpr int SMEM_BYTES  = SMEM_FLOATS * 4;   // ~178 KB, 1 CTA/SM

__device__ float g_wt[NWT];   // pre-transposed weights (written by prologue kernel)

typedef unsigned long long u64;

__device__ __forceinline__ u64 dup2(float x) {
    u64 r;
    asm("mov.b64 %0, {%1, %1};" : "=l"(r) : "f"(x));
    return r;
}
__device__ __forceinline__ u64 pack2(float lo, float hi) {
    u64 r;
    asm("mov.b64 %0, {%1, %2};" : "=l"(r) : "f"(lo), "f"(hi));
    return r;
}
__device__ __forceinline__ void unpack2(u64 v, float& lo, float& hi) {
    asm("mov.b64 {%0, %1}, %2;" : "=f"(lo), "=f"(hi) : "l"(v));
}
__device__ __forceinline__ void fma2(u64& acc, u64 w, u64 a) {
    asm("fma.rn.f32x2 %0, %1, %2, %0;" : "+l"(acc) : "l"(w), "l"(a));
}

__device__ __forceinline__ float eluf(float x) {
    return x > 0.f ? x : (__expf(x) - 1.f);
}

__device__ __forceinline__ float weno_side(float u0, float u1, float u2, float u3, float u4,
                                           float m0, float m1, float m2, float e) {
    const float c16 = 1.f / 6.f;
    float f0 = (11.f * u2 - 7.f * u3 + 2.f * u4) * c16;
    float f1 = (2.f * u1 + 5.f * u2 - u3) * c16;
    float f2 = (-u0 + 5.f * u1 + 2.f * u2) * c16;
    float t, b0, b1, b2;
    t = u2 - 2.f * u3 + u4;          b0 = (13.f / 12.f) * t * t;
    t = 3.f * u2 - 4.f * u3 + u4;    b0 += 0.25f * t * t;
    t = u1 - 2.f * u2 + u3;          b1 = (13.f / 12.f) * t * t;
    t = u1 - u3;                     b1 += 0.25f * t * t;
    t = u0 - 2.f * u1 + u2;          b2 = (13.f / 12.f) * t * t;
    t = u0 - 4.f * u1 + 3.f * u2;    b2 += 0.25f * t * t;
    b0 *= m0; b1 *= m1; b2 *= m2;
    float brs = (b2 - b0) * (b2 - b0);
    float q0 = (e + b0) * (e + b0);
    float q1 = (e + b1) * (e + b1);
    float q2 = (e + b2) * (e + b2);
    float o0 = __fdividef(0.1f, q0) * (brs + q0);
    float o1 = __fdividef(0.6f, q1) * (brs + q1);
    float o2 = __fdividef(0.3f, q2) * (brs + q2);
    float s = o0 + o1 + o2;
    return __fdividef(o0 * f0 + o1 * f1 + o2 * f2, s);
}

// Prologue: build transposed weight image once per launch (graph node 1).
__global__ void prep_weights(const float* __restrict__ w1, const float* __restrict__ b1,
                             const float* __restrict__ w2, const float* __restrict__ b2,
                             const float* __restrict__ w3, const float* __restrict__ b3,
                             const float* __restrict__ w4, const float* __restrict__ b4,
                             const float* __restrict__ w5, const float* __restrict__ b5,
                             const float* __restrict__ w6, const float* __restrict__ b6) {
    int i = blockIdx.x * blockDim.x + threadIdx.x;
    if (i < 100) g_wt[O_W1 + i] = w1[i];
    if (i < 20)  g_wt[O_B1 + i] = b1[i];
    if (i < 4000) {
        int oc = i / 100, r = i % 100;           // r = ic*5 + k
        g_wt[O_W2T + r * 40 + oc] = w2[i];
    }
    if (i < 40)  g_wt[O_B2 + i] = b2[i];
    if (i < 3200) {
        int oc = i / 40, ic = i % 40;
        g_wt[O_W3T + ic * 80 + oc] = w3[i];
    }
    if (i < 80)  g_wt[O_B3 + i] = b3[i];
    if (i < 3200) {
        int oc = i / 80, ic = i % 80;
        g_wt[O_W4T + ic * 40 + oc] = w4[i];
    }
    if (i < 40)  g_wt[O_B4 + i] = b4[i];
    if (i < 2400) {
        int oc = i / 120, r = i % 120;           // r = ic*3 + k
        g_wt[O_W5T + r * 20 + oc] = w5[i];
    }
    if (i < 20)  g_wt[O_B5 + i] = b5[i];
    if (i < 20)  g_wt[O_W6 + i] = w6[i];
    if (i == 0)  { g_wt[O_B6] = b6[0]; g_wt[O_B6 + 1] = 0.f; g_wt[O_B6 + 2] = 0.f; g_wt[O_B6 + 3] = 0.f; }
}

__global__ __launch_bounds__(NTH, 1)
void weno_fused(const float* __restrict__ uu, const float* __restrict__ e_p,
                float* __restrict__ out) {
    extern __shared__ float sm[];
    const int tid  = threadIdx.x;
    const int wid  = tid / 32;
    const int lane = tid % 32;
    const int o0 = blockIdx.x * TW;
    const int s   = wid & 1;            // span within the 256-wide row
    const int x0  = 128 * s + 4 * lane; // lane's 4-float chunk
    const int g   = wid >> 1;           // 0..9
    const int ocg5 = g % 5;             // oc-group for split layers
    const int h    = g / 5;             // ic-half for split layers (0 or 1)

    // ---- stage weights: straight float4 copy of the pre-transposed image ----
    {
        const float4* src = (const float4*)g_wt;
        float4* dst = (float4*)sm;
        #pragma unroll 2
        for (int i = tid; i < NWT / 4; i += NTH) dst[i] = src[i];
    }

    // ---- stage uu window [o0-4, o0+TW+10), index-clamped ----
    for (int i = tid; i < TW + 14; i += NTH) {
        int gg = o0 - 4 + i;
        gg = min(max(gg, 0), NTOT - 1);
        sm[O_UU + i] = uu[gg];
    }
    __syncthreads();

    // ---- dif window [o0-3, o0+TW+9); zero outside [0,N) ----
    for (int i = tid; i < TW + 12; i += NTH) {
        int gi = o0 - 3 + i;
        float v = 0.f;
        if ((unsigned)gi < (unsigned)NTOT) {
            int m1 = min(gi, NTOT - 2);
            int m2 = max(gi - 1, 0);
            int base = o0 - 4;
            v = 0.5f * ((sm[O_UU + m1 + 1 - base] - sm[O_UU + m1 - base]) +
                        (sm[O_UU + m2 + 1 - base] - sm[O_UU + m2 - base]));
        }
        sm[O_DIF + i] = v;
    }
    __syncthreads();

    // ---- conv1: 1->20, k5 pad2.  warp-contiguous, P=4.  A1 = X rows 0-19, base o0-1 ----
    for (int t = wid; t < 40; t += NWARP) {
        int c = t >> 1, ss = t & 1;
        int xx = 128 * ss + 4 * lane;
        float bias = sm[O_B1 + c];
        float acc[4];
        #pragma unroll
        for (int p = 0; p < 4; p++) acc[p] = bias;
        float4 d0 = *(const float4*)&sm[O_DIF + xx];
        float4 d1 = *(const float4*)&sm[O_DIF + xx + 4];
        float win[8] = {d0.x, d0.y, d0.z, d0.w, d1.x, d1.y, d1.z, d1.w};
        #pragma unroll
        for (int k = 0; k < 5; k++) {
            float w = sm[O_W1 + c * 5 + k];
            #pragma unroll
            for (int p = 0; p < 4; p++) acc[p] += w * win[p + k];
        }
        int pg = o0 - 1 + xx;
        float4 r;
        r.x = (unsigned)(pg + 0) < (unsigned)NTOT ? eluf(acc[0]) : 0.f;
        r.y = (unsigned)(pg + 1) < (unsigned)NTOT ? eluf(acc[1]) : 0.f;
        r.z = (unsigned)(pg + 2) < (unsigned)NTOT ? eluf(acc[2]) : 0.f;
        r.w = (unsigned)(pg + 3) < (unsigned)NTOT ? eluf(acc[3]) : 0.f;
        *(float4*)&sm[O_X + c * ST2 + xx] = r;
    }
    __syncthreads();

    // ==== conv2: 20->40, k5 pad2.  SPLIT-K: C=8, ic-halves of 10.  X(A1)->Y(A2) ====
    {
        int oc0 = ocg5 * 8;
        u64 acc[4][4];   // [oc pair][pos]
        if (h == 0) {
            float4 b0 = *(const float4*)&sm[O_B2 + oc0];
            float4 b1v = *(const float4*)&sm[O_B2 + oc0 + 4];
            u64 bp[4] = {pack2(b0.x, b0.y), pack2(b0.z, b0.w),
                         pack2(b1v.x, b1v.y), pack2(b1v.z, b1v.w)};
            #pragma unroll
            for (int j = 0; j < 4; j++)
                #pragma unroll
                for (int p = 0; p < 4; p++) acc[j][p] = bp[j];
        } else {
            #pragma unroll
            for (int j = 0; j < 4; j++)
                #pragma unroll
                for (int p = 0; p < 4; p++) acc[j][p] = 0ull;
        }
        int icB = h * 10;
        // software pipeline: preload next iteration's activations
        float4 v0 = *(const float4*)&sm[O_X + icB * ST2 + x0];
        float4 v1 = *(const float4*)&sm[O_X + icB * ST2 + x0 + 4];
        #pragma unroll 2
        for (int ic = icB; ic < icB + 10; ic++) {
            float4 n0, n1;
            if (ic + 1 < icB + 10) {
                n0 = *(const float4*)&sm[O_X + (ic + 1) * ST2 + x0];
                n1 = *(const float4*)&sm[O_X + (ic + 1) * ST2 + x0 + 4];
            }
            u64 dwin[8] = {dup2(v0.x), dup2(v0.y), dup2(v0.z), dup2(v0.w),
                           dup2(v1.x), dup2(v1.y), dup2(v1.z), dup2(v1.w)};
            #pragma unroll
            for (int k = 0; k < 5; k++) {
                ulonglong2 wA = *(const ulonglong2*)&sm[O_W2T + (ic * 5 + k) * 40 + oc0];
                ulonglong2 wB = *(const ulonglong2*)&sm[O_W2T + (ic * 5 + k) * 40 + oc0 + 4];
                #pragma unroll
                for (int p = 0; p < 4; p++) {
                    fma2(acc[0][p], wA.x, dwin[p + k]);
                    fma2(acc[1][p], wA.y, dwin[p + k]);
                    fma2(acc[2][p], wB.x, dwin[p + k]);
                    fma2(acc[3][p], wB.y, dwin[p + k]);
                }
            }
            v0 = n0; v1 = n1;
        }
        if (h == 1) {   // store raw partials into destination rows
            #pragma unroll
            for (int j = 0; j < 4; j++) {
                float lo[4], hi[4];
                #pragma unroll
                for (int p = 0; p < 4; p++) unpack2(acc[j][p], lo[p], hi[p]);
                *(float4*)&sm[O_Y + (oc0 + 2 * j) * ST2 + x0] =
                    make_float4(lo[0], lo[1], lo[2], lo[3]);
                *(float4*)&sm[O_Y + (oc0 + 2 * j + 1) * ST2 + x0] =
                    make_float4(hi[0], hi[1], hi[2], hi[3]);
            }
        }
        __syncthreads();
        if (h == 0) {   // add partner partial, activate, store final
            #pragma unroll
            for (int j = 0; j < 4; j++) {
                float lo[4], hi[4];
                #pragma unroll
                for (int p = 0; p < 4; p++) unpack2(acc[j][p], lo[p], hi[p]);
                float4 pl = *(const float4*)&sm[O_Y + (oc0 + 2 * j) * ST2 + x0];
                float4 ph = *(const float4*)&sm[O_Y + (oc0 + 2 * j + 1) * ST2 + x0];
                *(float4*)&sm[O_Y + (oc0 + 2 * j) * ST2 + x0] =
                    make_float4(eluf(lo[0] + pl.x), eluf(lo[1] + pl.y),
                                eluf(lo[2] + pl.z), eluf(lo[3] + pl.w));
                *(float4*)&sm[O_Y + (oc0 + 2 * j + 1) * ST2 + x0] =
                    make_float4(eluf(hi[0] + ph.x), eluf(hi[1] + ph.y),
                                eluf(hi[2] + ph.z), eluf(hi[3] + ph.w));
            }
        }
    }
    __syncthreads();

    // ---- conv3: 40->80, 1x1.  pos-packed f32x2, C=8, P=4.  Y(A2)->X(A3).  pipelined ----
    {
        int oc0 = g * 8;
        u64 acc[8][2];
        {
            float4 b0 = *(const float4*)&sm[O_B3 + oc0];
            float4 b1v = *(const float4*)&sm[O_B3 + oc0 + 4];
            float bb[8] = {b0.x, b0.y, b0.z, b0.w, b1v.x, b1v.y, b1v.z, b1v.w};
            #pragma unroll
            for (int c = 0; c < 8; c++) {
                u64 bd = dup2(bb[c]);
                acc[c][0] = bd; acc[c][1] = bd;
            }
        }
        ulonglong2 a = *(const ulonglong2*)&sm[O_Y + 0 * ST2 + x0];
        float4 w0 = *(const float4*)&sm[O_W3T + 0 * 80 + oc0];
        float4 w1v = *(const float4*)&sm[O_W3T + 0 * 80 + oc0 + 4];
        #pragma unroll 4
        for (int ic = 0; ic < 40; ic++) {
            ulonglong2 a_n;
            float4 w0_n, w1_n;
            if (ic + 1 < 40) {
                a_n  = *(const ulonglong2*)&sm[O_Y + (ic + 1) * ST2 + x0];
                w0_n = *(const float4*)&sm[O_W3T + (ic + 1) * 80 + oc0];
                w1_n = *(const float4*)&sm[O_W3T + (ic + 1) * 80 + oc0 + 4];
            }
            u64 dw[8] = {dup2(w0.x), dup2(w0.y), dup2(w0.z), dup2(w0.w),
                         dup2(w1v.x), dup2(w1v.y), dup2(w1v.z), dup2(w1v.w)};
            #pragma unroll
            for (int c = 0; c < 8; c++) {
                fma2(acc[c][0], dw[c], a.x);
                fma2(acc[c][1], dw[c], a.y);
            }
            a = a_n; w0 = w0_n; w1v = w1_n;
        }
        #pragma unroll
        for (int c = 0; c < 8; c++) {
            float f0, f1, f2, f3;
            unpack2(acc[c][0], f0, f1);
            unpack2(acc[c][1], f2, f3);
            *(float4*)&sm[O_X + (oc0 + c) * ST2 + x0] =
                make_float4(eluf(f0), eluf(f1), eluf(f2), eluf(f3));
        }
    }
    __syncthreads();

    // ==== conv4: 80->40, 1x1.  SPLIT-K: C=8, ic-halves of 40.  X(A3)->Y(A4).  pipelined ====
    {
        int oc0 = ocg5 * 8;
        u64 acc[8][2];
        if (h == 0) {
            float4 b0 = *(const float4*)&sm[O_B4 + oc0];
            float4 b1v = *(const float4*)&sm[O_B4 + oc0 + 4];
            float bb[8] = {b0.x, b0.y, b0.z, b0.w, b1v.x, b1v.y, b1v.z, b1v.w};
            #pragma unroll
            for (int c = 0; c < 8; c++) {
                u64 bd = dup2(bb[c]);
                acc[c][0] = bd; acc[c][1] = bd;
            }
        } else {
            #pragma unroll
            for (int c = 0; c < 8; c++) { acc[c][0] = 0ull; acc[c][1] = 0ull; }
        }
        int icB = h * 40;
        ulonglong2 a = *(const ulonglong2*)&sm[O_X + icB * ST2 + x0];
        float4 w0 = *(const float4*)&sm[O_W4T + icB * 40 + oc0];
        float4 w1v = *(const float4*)&sm[O_W4T + icB * 40 + oc0 + 4];
        #pragma unroll 4
        for (int ic = icB; ic < icB + 40; ic++) {
            ulonglong2 a_n;
            float4 w0_n, w1_n;
            if (ic + 1 < icB + 40) {
                a_n  = *(const ulonglong2*)&sm[O_X + (ic + 1) * ST2 + x0];
                w0_n = *(const float4*)&sm[O_W4T + (ic + 1) * 40 + oc0];
                w1_n = *(const float4*)&sm[O_W4T + (ic + 1) * 40 + oc0 + 4];
            }
            u64 dw[8] = {dup2(w0.x), dup2(w0.y), dup2(w0.z), dup2(w0.w),
                         dup2(w1v.x), dup2(w1v.y), dup2(w1v.z), dup2(w1v.w)};
            #pragma unroll
            for (int c = 0; c < 8; c++) {
                fma2(acc[c][0], dw[c], a.x);
                fma2(acc[c][1], dw[c], a.y);
            }
            a = a_n; w0 = w0_n; w1v = w1_n;
        }
        if (h == 1) {   // raw partials
            #pragma unroll
            for (int c = 0; c < 8; c++) {
                float f0, f1, f2, f3;
                unpack2(acc[c][0], f0, f1);
                unpack2(acc[c][1], f2, f3);
                *(float4*)&sm[O_Y + (oc0 + c) * ST2 + x0] = make_float4(f0, f1, f2, f3);
            }
        }
        __syncthreads();
        if (h == 0) {
            int p0 = o0 + 1 + x0;
            float m0 = (unsigned)(p0 + 0) < (unsigned)NTOT ? 1.f : 0.f;
            float m1 = (unsigned)(p0 + 1) < (unsigned)NTOT ? 1.f : 0.f;
            float m2 = (unsigned)(p0 + 2) < (unsigned)NTOT ? 1.f : 0.f;
            float m3 = (unsigned)(p0 + 3) < (unsigned)NTOT ? 1.f : 0.f;
            #pragma unroll
            for (int c = 0; c < 8; c++) {
                float f0, f1, f2, f3;
                unpack2(acc[c][0], f0, f1);
                unpack2(acc[c][1], f2, f3);
                float4 pp = *(const float4*)&sm[O_Y + (oc0 + c) * ST2 + x0];
                *(float4*)&sm[O_Y + (oc0 + c) * ST2 + x0] =
                    make_float4(m0 * eluf(f0 + pp.x), m1 * eluf(f1 + pp.y),
                                m2 * eluf(f2 + pp.z), m3 * eluf(f3 + pp.w));
            }
        }
    }
    __syncthreads();

    // ==== conv5: 40->20, k3 pad1.  SPLIT-K: C=4, ic-halves of 20.  Y(A4)->X(A5) ====
    {
        int oc0 = ocg5 * 4;
        u64 acc[2][4];
        if (h == 0) {
            float4 bv = *(const float4*)&sm[O_B5 + oc0];
            u64 b01 = pack2(bv.x, bv.y), b23 = pack2(bv.z, bv.w);
            #pragma unroll
            for (int p = 0; p < 4; p++) { acc[0][p] = b01; acc[1][p] = b23; }
        } else {
            #pragma unroll
            for (int p = 0; p < 4; p++) { acc[0][p] = 0ull; acc[1][p] = 0ull; }
        }
        int icB = h * 20;
        float4 v0 = *(const float4*)&sm[O_Y + icB * ST2 + x0];
        float2 v1 = *(const float2*)&sm[O_Y + icB * ST2 + x0 + 4];
        #pragma unroll 4
        for (int ic = icB; ic < icB + 20; ic++) {
            float4 n0; float2 n1;
            if (ic + 1 < icB + 20) {
                n0 = *(const float4*)&sm[O_Y + (ic + 1) * ST2 + x0];
                n1 = *(const float2*)&sm[O_Y + (ic + 1) * ST2 + x0 + 4];
            }
            u64 dwin[6] = {dup2(v0.x), dup2(v0.y), dup2(v0.z), dup2(v0.w),
                           dup2(v1.x), dup2(v1.y)};
            #pragma unroll
            for (int k = 0; k < 3; k++) {
                ulonglong2 w = *(const ulonglong2*)&sm[O_W5T + (ic * 3 + k) * 20 + oc0];
                #pragma unroll
                for (int p = 0; p < 4; p++) {
                    fma2(acc[0][p], w.x, dwin[p + k]);
                    fma2(acc[1][p], w.y, dwin[p + k]);
                }
            }
            v0 = n0; v1 = n1;
        }
        if (h == 1) {   // raw partials into X rows oc0..oc0+3
            #pragma unroll
            for (int j = 0; j < 2; j++) {
                float lo[4], hi[4];
                #pragma unroll
                for (int p = 0; p < 4; p++) unpack2(acc[j][p], lo[p], hi[p]);
                *(float4*)&sm[O_X + (oc0 + 2 * j) * ST2 + x0] =
                    make_float4(lo[0], lo[1], lo[2], lo[3]);
                *(float4*)&sm[O_X + (oc0 + 2 * j + 1) * ST2 + x0] =
                    make_float4(hi[0], hi[1], hi[2], hi[3]);
            }
        }
        __syncthreads();
        if (h == 0) {
            #pragma unroll
            for (int j = 0; j < 2; j++) {
                float lo[4], hi[4];
                #pragma unroll
                for (int p = 0; p < 4; p++) unpack2(acc[j][p], lo[p], hi[p]);
                float4 pl = *(const float4*)&sm[O_X + (oc0 + 2 * j) * ST2 + x0];
                float4 ph = *(const float4*)&sm[O_X + (oc0 + 2 * j + 1) * ST2 + x0];
                *(float4*)&sm[O_X + (oc0 + 2 * j) * ST2 + x0] =
                    make_float4(eluf(lo[0] + pl.x), eluf(lo[1] + pl.y),
                                eluf(lo[2] + pl.z), eluf(lo[3] + pl.w));
                *(float4*)&sm[O_X + (oc0 + 2 * j + 1) * ST2 + x0] =
                    make_float4(eluf(hi[0] + ph.x), eluf(hi[1] + ph.y),
                                eluf(hi[2] + ph.z), eluf(hi[3] + ph.w));
            }
        }
    }
    __syncthreads();

    // ---- conv6 + sigmoid + bias: beta_mult, base o0+2, width TW+2=250 ----
    for (int x = tid; x < TW + 2; x += NTH) {
        float acc = sm[O_B6];
        #pragma unroll
        for (int c = 0; c < 20; c++) acc += sm[O_W6 + c] * sm[O_X + c * ST2 + x];
        sm[O_BM + x] = __fdividef(1.f, 1.f + __expf(-acc)) + 0.1f;
    }
    __syncthreads();

    // ---- WENO5 flux ----
    int j = o0 + tid;
    if (tid < TW && j < NOUT) {
        const float* U = &sm[O_UU + tid + 5];   // uu[j+1 .. j+6]
        float v0 = U[0], v1 = U[1], v2 = U[2], v3 = U[3], v4 = U[4], v5 = U[5];
        float m0 = sm[O_BM + tid];
        float m1 = sm[O_BM + tid + 1];
        float m2 = sm[O_BM + tid + 2];
        float e = e_p[0];
        float fluxp = weno_side(v1, v2, v3, v4, v5, m0, m1, m2, e);
        float fluxn = weno_side(v0, v1, v2, v3, v4, m0, m1, m2, e);
        out[j] = fluxp - fluxn;
    }
}

extern "C" void kernel_launch(void* const* d_in, const int* in_sizes, int n_in,
                              void* d_out, int out_size) {
    const float* uu = (const float*)d_in[0];
    const float* e  = (const float*)d_in[1];
    const float* w1 = (const float*)d_in[2];
    const float* b1 = (const float*)d_in[3];
    const float* w2 = (const float*)d_in[4];
    const float* b2 = (const float*)d_in[5];
    const float* w3 = (const float*)d_in[6];
    const float* b3 = (const float*)d_in[7];
    const float* w4 = (const float*)d_in[8];
    const float* b4 = (const float*)d_in[9];
    const float* w5 = (const float*)d_in[10];
    const float* b5 = (const float*)d_in[11];
    const float* w6 = (const float*)d_in[12];
    const float* b6 = (const float*)d_in[13];
    float* out = (float*)d_out;

    // node 1: build transposed weight image
    prep_weights<<<16, 256>>>(w1, b1, w2, b2, w3, b3, w4, b4, w5, b5, w6, b6);

    // node 2: fused WENO network
    cudaFuncSetAttribute(weno_fused, cudaFuncAttributeMaxDynamicSharedMemorySize, SMEM_BYTES);
    int grid = (NOUT + TW - 1) / TW;
    weno_fused<<<grid, NTH, SMEM_BYTES>>>(uu, e, out);
}

// round 15
// speedup vs baseline: 1.0955x; 1.0955x over previous
#include <cuda_runtime.h>
#include <math.h>

#define NTH 640
#define NWARP 20
#define TW  248           // outputs per block; row width 256 = 2 warp-spans

constexpr int NTOT = 2097152;
constexpr int NOUT = NTOT - 6;
constexpr int ST2  = 256;  // activation row stride (floats)

// ---- weight scratch layout (floats); transposed oc-contiguous ----
constexpr int O_W1  = 0;                 // 100   w1[oc][k]
constexpr int O_B1  = 100;               // 20
constexpr int O_W2T = 120;               // 4000  T2[(ic*5+k)*40 + oc]
constexpr int O_B2  = 4120;              // 40
constexpr int O_W3T = 4160;              // 3200  T3[ic*80 + oc]
constexpr int O_B3  = 7360;              // 80
constexpr int O_W4T = 7440;              // 3200  T4[ic*40 + oc]
constexpr int O_B4  = 10640;             // 40
constexpr int O_W5T = 10680;             // 2400  T5[(ic*3+k)*20 + oc]
constexpr int O_B5  = 13080;             // 20
constexpr int O_W6  = 13100;             // 20
constexpr int O_B6  = 13120;             // 1 (+3 pad)
constexpr int NWT   = 13124;             // total weight floats (divisible by 4)
// ---- activation area (shared memory) ----
constexpr int O_UU  = 13124;             // alloc 264 (need TW+14=262)
constexpr int O_DIF = O_UU + 264;        // alloc 264 (need TW+12=260)
constexpr int O_BM  = O_DIF + 264;       // alloc 256 (need TW+2=250)
constexpr int O_Y   = O_BM + 256;        // 40*ST2  (A2, A4)
constexpr int O_X   = O_Y + 40 * ST2;    // 80*ST2  (A1 rows 0-19, A3 all, A5 rows 0-19)
constexpr int SMEM_FLOATS = O_X + 80 * ST2;
constexpr int SMEM_BYTES  = SMEM_FLOATS * 4;   // ~178 KB, 1 CTA/SM

__device__ float g_wt[NWT];   // pre-transposed weights (written by prologue kernel)

typedef unsigned long long u64;

__device__ __forceinline__ u64 dup2(float x) {
    u64 r;
    asm("mov.b64 %0, {%1, %1};" : "=l"(r) : "f"(x));
    return r;
}
__device__ __forceinline__ u64 pack2(float lo, float hi) {
    u64 r;
    asm("mov.b64 %0, {%1, %2};" : "=l"(r) : "f"(lo), "f"(hi));
    return r;
}
__device__ __forceinline__ void unpack2(u64 v, float& lo, float& hi) {
    asm("mov.b64 {%0, %1}, %2;" : "=f"(lo), "=f"(hi) : "l"(v));
}
__device__ __forceinline__ void fma2(u64& acc, u64 w, u64 a) {
    asm("fma.rn.f32x2 %0, %1, %2, %0;" : "+l"(acc) : "l"(w), "l"(a));
}

__device__ __forceinline__ float eluf(float x) {
    return x > 0.f ? x : (__expf(x) - 1.f);
}

__device__ __forceinline__ float weno_side(float u0, float u1, float u2, float u3, float u4,
                                           float m0, float m1, float m2, float e) {
    const float c16 = 1.f / 6.f;
    float f0 = (11.f * u2 - 7.f * u3 + 2.f * u4) * c16;
    float f1 = (2.f * u1 + 5.f * u2 - u3) * c16;
    float f2 = (-u0 + 5.f * u1 + 2.f * u2) * c16;
    float t, b0, b1, b2;
    t = u2 - 2.f * u3 + u4;          b0 = (13.f / 12.f) * t * t;
    t = 3.f * u2 - 4.f * u3 + u4;    b0 += 0.25f * t * t;
    t = u1 - 2.f * u2 + u3;          b1 = (13.f / 12.f) * t * t;
    t = u1 - u3;                     b1 += 0.25f * t * t;
    t = u0 - 2.f * u1 + u2;          b2 = (13.f / 12.f) * t * t;
    t = u0 - 4.f * u1 + 3.f * u2;    b2 += 0.25f * t * t;
    b0 *= m0; b1 *= m1; b2 *= m2;
    float brs = (b2 - b0) * (b2 - b0);
    float q0 = (e + b0) * (e + b0);
    float q1 = (e + b1) * (e + b1);
    float q2 = (e + b2) * (e + b2);
    float o0 = __fdividef(0.1f, q0) * (brs + q0);
    float o1 = __fdividef(0.6f, q1) * (brs + q1);
    float o2 = __fdividef(0.3f, q2) * (brs + q2);
    float s = o0 + o1 + o2;
    return __fdividef(o0 * f0 + o1 * f1 + o2 * f2, s);
}

// Prologue: build transposed weight image once per launch (graph node 1).
__global__ void prep_weights(const float* __restrict__ w1, const float* __restrict__ b1,
                             const float* __restrict__ w2, const float* __restrict__ b2,
                             const float* __restrict__ w3, const float* __restrict__ b3,
                             const float* __restrict__ w4, const float* __restrict__ b4,
                             const float* __restrict__ w5, const float* __restrict__ b5,
                             const float* __restrict__ w6, const float* __restrict__ b6) {
    int i = blockIdx.x * blockDim.x + threadIdx.x;
    if (i < 100) g_wt[O_W1 + i] = w1[i];
    if (i < 20)  g_wt[O_B1 + i] = b1[i];
    if (i < 4000) {
        int oc = i / 100, r = i % 100;           // r = ic*5 + k
        g_wt[O_W2T + r * 40 + oc] = w2[i];
    }
    if (i < 40)  g_wt[O_B2 + i] = b2[i];
    if (i < 3200) {
        int oc = i / 40, ic = i % 40;
        g_wt[O_W3T + ic * 80 + oc] = w3[i];
    }
    if (i < 80)  g_wt[O_B3 + i] = b3[i];
    if (i < 3200) {
        int oc = i / 80, ic = i % 80;
        g_wt[O_W4T + ic * 40 + oc] = w4[i];
    }
    if (i < 40)  g_wt[O_B4 + i] = b4[i];
    if (i < 2400) {
        int oc = i / 120, r = i % 120;           // r = ic*3 + k
        g_wt[O_W5T + r * 20 + oc] = w5[i];
    }
    if (i < 20)  g_wt[O_B5 + i] = b5[i];
    if (i < 20)  g_wt[O_W6 + i] = w6[i];
    if (i == 0)  { g_wt[O_B6] = b6[0]; g_wt[O_B6 + 1] = 0.f; g_wt[O_B6 + 2] = 0.f; g_wt[O_B6 + 3] = 0.f; }
}

__global__ __launch_bounds__(NTH, 1)
void weno_fused(const float* __restrict__ uu, const float* __restrict__ e_p,
                float* __restrict__ out) {
    extern __shared__ float sm[];
    const int tid  = threadIdx.x;
    const int wid  = tid / 32;
    const int lane = tid % 32;
    const int o0 = blockIdx.x * TW;
    const int s   = wid & 1;            // span within the 256-wide row
    const int x0  = 128 * s + 4 * lane; // lane's 4-float chunk
    const int g   = wid >> 1;           // 0..9
    const int ocg5 = g % 5;             // oc-group for split layers
    const int h    = g / 5;             // ic-half for split layers (0 or 1)

    // ---- stage weights: straight float4 copy of the pre-transposed image ----
    {
        const float4* src = (const float4*)g_wt;
        float4* dst = (float4*)sm;
        #pragma unroll 2
        for (int i = tid; i < NWT / 4; i += NTH) dst[i] = src[i];
    }

    // ---- stage uu window [o0-4, o0+TW+10), index-clamped ----
    for (int i = tid; i < TW + 14; i += NTH) {
        int gg = o0 - 4 + i;
        gg = min(max(gg, 0), NTOT - 1);
        sm[O_UU + i] = uu[gg];
    }
    __syncthreads();

    // ---- dif window [o0-3, o0+TW+9); zero outside [0,N) ----
    for (int i = tid; i < TW + 12; i += NTH) {
        int gi = o0 - 3 + i;
        float v = 0.f;
        if ((unsigned)gi < (unsigned)NTOT) {
            int m1 = min(gi, NTOT - 2);
            int m2 = max(gi - 1, 0);
            int base = o0 - 4;
            v = 0.5f * ((sm[O_UU + m1 + 1 - base] - sm[O_UU + m1 - base]) +
                        (sm[O_UU + m2 + 1 - base] - sm[O_UU + m2 - base]));
        }
        sm[O_DIF + i] = v;
    }
    __syncthreads();

    // ---- conv1: 1->20, k5 pad2.  warp-contiguous, P=4.  A1 = X rows 0-19, base o0-1 ----
    for (int t = wid; t < 40; t += NWARP) {
        int c = t >> 1, ss = t & 1;
        int xx = 128 * ss + 4 * lane;
        float bias = sm[O_B1 + c];
        float acc[4];
        #pragma unroll
        for (int p = 0; p < 4; p++) acc[p] = bias;
        float4 d0 = *(const float4*)&sm[O_DIF + xx];
        float4 d1 = *(const float4*)&sm[O_DIF + xx + 4];
        float win[8] = {d0.x, d0.y, d0.z, d0.w, d1.x, d1.y, d1.z, d1.w};
        #pragma unroll
        for (int k = 0; k < 5; k++) {
            float w = sm[O_W1 + c * 5 + k];
            #pragma unroll
            for (int p = 0; p < 4; p++) acc[p] += w * win[p + k];
        }
        int pg = o0 - 1 + xx;
        float4 r;
        r.x = (unsigned)(pg + 0) < (unsigned)NTOT ? eluf(acc[0]) : 0.f;
        r.y = (unsigned)(pg + 1) < (unsigned)NTOT ? eluf(acc[1]) : 0.f;
        r.z = (unsigned)(pg + 2) < (unsigned)NTOT ? eluf(acc[2]) : 0.f;
        r.w = (unsigned)(pg + 3) < (unsigned)NTOT ? eluf(acc[3]) : 0.f;
        *(float4*)&sm[O_X + c * ST2 + xx] = r;
    }
    __syncthreads();

    // ==== conv2: 20->40, k5 pad2.  SPLIT-K: C=8, ic-halves of 10.  X(A1)->Y(A2) ====
    {
        int oc0 = ocg5 * 8;
        u64 acc[4][4];   // [oc pair][pos]
        if (h == 0) {
            float4 b0 = *(const float4*)&sm[O_B2 + oc0];
            float4 b1v = *(const float4*)&sm[O_B2 + oc0 + 4];
            u64 bp[4] = {pack2(b0.x, b0.y), pack2(b0.z, b0.w),
                         pack2(b1v.x, b1v.y), pack2(b1v.z, b1v.w)};
            #pragma unroll
            for (int j = 0; j < 4; j++)
                #pragma unroll
                for (int p = 0; p < 4; p++) acc[j][p] = bp[j];
        } else {
            #pragma unroll
            for (int j = 0; j < 4; j++)
                #pragma unroll
                for (int p = 0; p < 4; p++) acc[j][p] = 0ull;
        }
        int icB = h * 10;
        #pragma unroll 2
        for (int ic = icB; ic < icB + 10; ic++) {
            const float* ar = &sm[O_X + ic * ST2 + x0];
            float4 v0 = *(const float4*)(ar);
            float4 v1 = *(const float4*)(ar + 4);
            u64 dwin[8] = {dup2(v0.x), dup2(v0.y), dup2(v0.z), dup2(v0.w),
                           dup2(v1.x), dup2(v1.y), dup2(v1.z), dup2(v1.w)};
            #pragma unroll
            for (int k = 0; k < 5; k++) {
                ulonglong2 wA = *(const ulonglong2*)&sm[O_W2T + (ic * 5 + k) * 40 + oc0];
                ulonglong2 wB = *(const ulonglong2*)&sm[O_W2T + (ic * 5 + k) * 40 + oc0 + 4];
                #pragma unroll
                for (int p = 0; p < 4; p++) {
                    fma2(acc[0][p], wA.x, dwin[p + k]);
                    fma2(acc[1][p], wA.y, dwin[p + k]);
                    fma2(acc[2][p], wB.x, dwin[p + k]);
                    fma2(acc[3][p], wB.y, dwin[p + k]);
                }
            }
        }
        if (h == 1) {   // store raw partials into destination rows
            #pragma unroll
            for (int j = 0; j < 4; j++) {
                float lo[4], hi[4];
                #pragma unroll
                for (int p = 0; p < 4; p++) unpack2(acc[j][p], lo[p], hi[p]);
                *(float4*)&sm[O_Y + (oc0 + 2 * j) * ST2 + x0] =
                    make_float4(lo[0], lo[1], lo[2], lo[3]);
                *(float4*)&sm[O_Y + (oc0 + 2 * j + 1) * ST2 + x0] =
                    make_float4(hi[0], hi[1], hi[2], hi[3]);
            }
        }
        __syncthreads();
        if (h == 0) {   // add partner partial, activate, store final
            #pragma unroll
            for (int j = 0; j < 4; j++) {
                float lo[4], hi[4];
                #pragma unroll
                for (int p = 0; p < 4; p++) unpack2(acc[j][p], lo[p], hi[p]);
                float4 pl = *(const float4*)&sm[O_Y + (oc0 + 2 * j) * ST2 + x0];
                float4 ph = *(const float4*)&sm[O_Y + (oc0 + 2 * j + 1) * ST2 + x0];
                *(float4*)&sm[O_Y + (oc0 + 2 * j) * ST2 + x0] =
                    make_float4(eluf(lo[0] + pl.x), eluf(lo[1] + pl.y),
                                eluf(lo[2] + pl.z), eluf(lo[3] + pl.w));
                *(float4*)&sm[O_Y + (oc0 + 2 * j + 1) * ST2 + x0] =
                    make_float4(eluf(hi[0] + ph.x), eluf(hi[1] + ph.y),
                                eluf(hi[2] + ph.z), eluf(hi[3] + ph.w));
            }
        }
    }
    __syncthreads();

    // ---- conv3: 40->80, 1x1.  pos-packed f32x2, C=8, P=4.  Y(A2)->X(A3) ----
    {
        int oc0 = g * 8;
        u64 acc[8][2];
        {
            float4 b0 = *(const float4*)&sm[O_B3 + oc0];
            float4 b1v = *(const float4*)&sm[O_B3 + oc0 + 4];
            float bb[8] = {b0.x, b0.y, b0.z, b0.w, b1v.x, b1v.y, b1v.z, b1v.w};
            #pragma unroll
            for (int c = 0; c < 8; c++) {
                u64 bd = dup2(bb[c]);
                acc[c][0] = bd; acc[c][1] = bd;
            }
        }
        #pragma unroll 4
        for (int ic = 0; ic < 40; ic++) {
            ulonglong2 a = *(const ulonglong2*)&sm[O_Y + ic * ST2 + x0];
            float4 w0 = *(const float4*)&sm[O_W3T + ic * 80 + oc0];
            float4 w1v = *(const float4*)&sm[O_W3T + ic * 80 + oc0 + 4];
            u64 dw[8] = {dup2(w0.x), dup2(w0.y), dup2(w0.z), dup2(w0.w),
                         dup2(w1v.x), dup2(w1v.y), dup2(w1v.z), dup2(w1v.w)};
            #pragma unroll
            for (int c = 0; c < 8; c++) {
                fma2(acc[c][0], dw[c], a.x);
                fma2(acc[c][1], dw[c], a.y);
            }
        }
        #pragma unroll
        for (int c = 0; c < 8; c++) {
            float f0, f1, f2, f3;
            unpack2(acc[c][0], f0, f1);
            unpack2(acc[c][1], f2, f3);
            *(float4*)&sm[O_X + (oc0 + c) * ST2 + x0] =
                make_float4(eluf(f0), eluf(f1), eluf(f2), eluf(f3));
        }
    }
    __syncthreads();

    // ==== conv4: 80->40, 1x1.  SPLIT-K: C=8, ic-halves of 40.  X(A3)->Y(A4) ====
    {
        int oc0 = ocg5 * 8;
        u64 acc[8][2];
        if (h == 0) {
            float4 b0 = *(const float4*)&sm[O_B4 + oc0];
            float4 b1v = *(const float4*)&sm[O_B4 + oc0 + 4];
            float bb[8] = {b0.x, b0.y, b0.z, b0.w, b1v.x, b1v.y, b1v.z, b1v.w};
            #pragma unroll
            for (int c = 0; c < 8; c++) {
                u64 bd = dup2(bb[c]);
                acc[c][0] = bd; acc[c][1] = bd;
            }
        } else {
            #pragma unroll
            for (int c = 0; c < 8; c++) { acc[c][0] = 0ull; acc[c][1] = 0ull; }
        }
        int icB = h * 40;
        #pragma unroll 4
        for (int ic = icB; ic < icB + 40; ic++) {
            ulonglong2 a = *(const ulonglong2*)&sm[O_X + ic * ST2 + x0];
            float4 w0 = *(const float4*)&sm[O_W4T + ic * 40 + oc0];
            float4 w1v = *(const float4*)&sm[O_W4T + ic * 40 + oc0 + 4];
            u64 dw[8] = {dup2(w0.x), dup2(w0.y), dup2(w0.z), dup2(w0.w),
                         dup2(w1v.x), dup2(w1v.y), dup2(w1v.z), dup2(w1v.w)};
            #pragma unroll
            for (int c = 0; c < 8; c++) {
                fma2(acc[c][0], dw[c], a.x);
                fma2(acc[c][1], dw[c], a.y);
            }
        }
        if (h == 1) {   // raw partials
            #pragma unroll
            for (int c = 0; c < 8; c++) {
                float f0, f1, f2, f3;
                unpack2(acc[c][0], f0, f1);
                unpack2(acc[c][1], f2, f3);
                *(float4*)&sm[O_Y + (oc0 + c) * ST2 + x0] = make_float4(f0, f1, f2, f3);
            }
        }
        __syncthreads();
        if (h == 0) {
            int p0 = o0 + 1 + x0;
            float m0 = (unsigned)(p0 + 0) < (unsigned)NTOT ? 1.f : 0.f;
            float m1 = (unsigned)(p0 + 1) < (unsigned)NTOT ? 1.f : 0.f;
            float m2 = (unsigned)(p0 + 2) < (unsigned)NTOT ? 1.f : 0.f;
            float m3 = (unsigned)(p0 + 3) < (unsigned)NTOT ? 1.f : 0.f;
            #pragma unroll
            for (int c = 0; c < 8; c++) {
                float f0, f1, f2, f3;
                unpack2(acc[c][0], f0, f1);
                unpack2(acc[c][1], f2, f3);
                float4 pp = *(const float4*)&sm[O_Y + (oc0 + c) * ST2 + x0];
                *(float4*)&sm[O_Y + (oc0 + c) * ST2 + x0] =
                    make_float4(m0 * eluf(f0 + pp.x), m1 * eluf(f1 + pp.y),
                                m2 * eluf(f2 + pp.z), m3 * eluf(f3 + pp.w));
            }
        }
    }
    __syncthreads();

    // ==== conv5: 40->20, k3 pad1.  SPLIT-K: C=4, ic-halves of 20.  Y(A4)->X(A5) ====
    {
        int oc0 = ocg5 * 4;
        u64 acc[2][4];
        if (h == 0) {
            float4 bv = *(const float4*)&sm[O_B5 + oc0];
            u64 b01 = pack2(bv.x, bv.y), b23 = pack2(bv.z, bv.w);
            #pragma unroll
            for (int p = 0; p < 4; p++) { acc[0][p] = b01; acc[1][p] = b23; }
        } else {
            #pragma unroll
            for (int p = 0; p < 4; p++) { acc[0][p] = 0ull; acc[1][p] = 0ull; }
        }
        int icB = h * 20;
        #pragma unroll 4
        for (int ic = icB; ic < icB + 20; ic++) {
            const float* ar = &sm[O_Y + ic * ST2 + x0];
            float4 v0 = *(const float4*)(ar);
            float2 v1 = *(const float2*)(ar + 4);
            u64 dwin[6] = {dup2(v0.x), dup2(v0.y), dup2(v0.z), dup2(v0.w),
                           dup2(v1.x), dup2(v1.y)};
            #pragma unroll
            for (int k = 0; k < 3; k++) {
                ulonglong2 w = *(const ulonglong2*)&sm[O_W5T + (ic * 3 + k) * 20 + oc0];
                #pragma unroll
                for (int p = 0; p < 4; p++) {
                    fma2(acc[0][p], w.x, dwin[p + k]);
                    fma2(acc[1][p], w.y, dwin[p + k]);
                }
            }
        }
        if (h == 1) {   // raw partials into X rows oc0..oc0+3
            #pragma unroll
            for (int j = 0; j < 2; j++) {
                float lo[4], hi[4];
                #pragma unroll
                for (int p = 0; p < 4; p++) unpack2(acc[j][p], lo[p], hi[p]);
                *(float4*)&sm[O_X + (oc0 + 2 * j) * ST2 + x0] =
                    make_float4(lo[0], lo[1], lo[2], lo[3]);
                *(float4*)&sm[O_X + (oc0 + 2 * j + 1) * ST2 + x0] =
                    make_float4(hi[0], hi[1], hi[2], hi[3]);
            }
        }
        __syncthreads();
        if (h == 0) {
            #pragma unroll
            for (int j = 0; j < 2; j++) {
                float lo[4], hi[4];
                #pragma unroll
                for (int p = 0; p < 4; p++) unpack2(acc[j][p], lo[p], hi[p]);
                float4 pl = *(const float4*)&sm[O_X + (oc0 + 2 * j) * ST2 + x0];
                float4 ph = *(const float4*)&sm[O_X + (oc0 + 2 * j + 1) * ST2 + x0];
                *(float4*)&sm[O_X + (oc0 + 2 * j) * ST2 + x0] =
                    make_float4(eluf(lo[0] + pl.x), eluf(lo[1] + pl.y),
                                eluf(lo[2] + pl.z), eluf(lo[3] + pl.w));
                *(float4*)&sm[O_X + (oc0 + 2 * j + 1) * ST2 + x0] =
                    make_float4(eluf(hi[0] + ph.x), eluf(hi[1] + ph.y),
                                eluf(hi[2] + ph.z), eluf(hi[3] + ph.w));
            }
        }
    }
    __syncthreads();

    // ---- conv6 + sigmoid + bias: beta_mult, base o0+2, width TW+2=250 ----
    for (int x = tid; x < TW + 2; x += NTH) {
        float acc = sm[O_B6];
        #pragma unroll
        for (int c = 0; c < 20; c++) acc += sm[O_W6 + c] * sm[O_X + c * ST2 + x];
        sm[O_BM + x] = __fdividef(1.f, 1.f + __expf(-acc)) + 0.1f;
    }
    __syncthreads();

    // ---- WENO5 flux ----
    int j = o0 + tid;
    if (tid < TW && j < NOUT) {
        const float* U = &sm[O_UU + tid + 5];   // uu[j+1 .. j+6]
        float v0 = U[0], v1 = U[1], v2 = U[2], v3 = U[3], v4 = U[4], v5 = U[5];
        float m0 = sm[O_BM + tid];
        float m1 = sm[O_BM + tid + 1];
        float m2 = sm[O_BM + tid + 2];
        float e = e_p[0];
        float fluxp = weno_side(v1, v2, v3, v4, v5, m0, m1, m2, e);
        float fluxn = weno_side(v0, v1, v2, v3, v4, m0, m1, m2, e);
        out[j] = fluxp - fluxn;
    }
}

extern "C" void kernel_launch(void* const* d_in, const int* in_sizes, int n_in,
                              void* d_out, int out_size) {
    const float* uu = (const float*)d_in[0];
    const float* e  = (const float*)d_in[1];
    const float* w1 = (const float*)d_in[2];
    const float* b1 = (const float*)d_in[3];
    const float* w2 = (const float*)d_in[4];
    const float* b2 = (const float*)d_in[5];
    const float* w3 = (const float*)d_in[6];
    const float* b3 = (const float*)d_in[7];
    const float* w4 = (const float*)d_in[8];
    const float* b4 = (const float*)d_in[9];
    const float* w5 = (const float*)d_in[10];
    const float* b5 = (const float*)d_in[11];
    const float* w6 = (const float*)d_in[12];
    const float* b6 = (const float*)d_in[13];
    float* out = (float*)d_out;

    // node 1: build transposed weight image
    prep_weights<<<16, 256>>>(w1, b1, w2, b2, w3, b3, w4, b4, w5, b5, w6, b6);

    // node 2: fused WENO network
    cudaFuncSetAttribute(weno_fused, cudaFuncAttributeMaxDynamicSharedMemorySize, SMEM_BYTES);
    int grid = (NOUT + TW - 1) / TW;
    weno_fused<<<grid, NTH, SMEM_BYTES>>>(uu, e, out);
}